// round 4
// baseline (speedup 1.0000x reference)
#include <cuda_runtime.h>
#include <stdint.h>
#include <math.h>

#define Bq 512
#define Tq 512
#define Fq 52
#define Eq 64
#define Hq 128
#define G4q 512
#define NROWS (Bq*Tq)

// Scratch (device globals; no dynamic allocation allowed)
__device__ float g_henc[NROWS * Eq];          // 64 MB  [row][64]
__device__ float g_gx[NROWS * G4q];           // 512 MB [t][b][512]
__device__ float g_hfin[Bq * Hq];             // final hidden state

// ---------------------------------------------------------------------------
// helpers
// ---------------------------------------------------------------------------
__device__ __forceinline__ unsigned smem_u32(const void* p) {
    unsigned a;
    asm("{ .reg .u64 t; cvta.to.shared.u64 t, %1; cvt.u32.u64 %0, t; }"
        : "=r"(a) : "l"(p));
    return a;
}

__device__ __forceinline__ float sigf(float x) {
    return __fdividef(1.f, 1.f + __expf(-x));
}
__device__ __forceinline__ float tanhf_s(float x) {
    float ax = fabsf(x);
    float e  = __expf(-2.f * ax);            // in (0,1], never overflows
    float r  = __fdividef(1.f - e, 1.f + e);
    return copysignf(r, x);
}

// ---------------------------------------------------------------------------
// Fused encoder: h_enc = relu(relu(x @ W1^T + b1) @ W2^T + b2)
// ---------------------------------------------------------------------------
#define ENC_SMEM_FLOATS (64*53 + 52*128 + 64*128 + 128*64 + 128 + 64)

__global__ __launch_bounds__(256) void enc_kernel(
    const float* __restrict__ x,
    const float* __restrict__ W1, const float* __restrict__ b1,
    const float* __restrict__ W2, const float* __restrict__ b2)
{
    extern __shared__ float sm[];
    float* xs  = sm;                 // [64][53]
    float* w1t = xs  + 64*53;        // [52][128]
    float* h1s = w1t + 52*128;       // [64][128]
    float* w2t = h1s + 64*128;       // [128][64]
    float* b1s = w2t + 128*64;
    float* b2s = b1s + 128;

    const int tid = threadIdx.x;
    const int row0 = blockIdx.x * 64;

    for (int idx = tid; idx < 128*52; idx += 256) {
        int c = idx / 52, k = idx % 52;
        w1t[k*128 + c] = W1[idx];
    }
    for (int idx = tid; idx < 64*128; idx += 256) {
        int e = idx / 128, k = idx % 128;
        w2t[k*64 + e] = W2[idx];
    }
    if (tid < 128) b1s[tid] = b1[tid];
    if (tid < 64)  b2s[tid] = b2[tid];
    for (int idx = tid; idx < 64*52; idx += 256) {
        int r = idx / 52, k = idx % 52;
        xs[r*53 + k] = x[(size_t)(row0 + r) * Fq + k];
    }
    __syncthreads();

    // layer 1
    {
        const int cg = tid & 15, rg = tid >> 4;
        const int c0 = cg * 8, r0 = rg * 4;
        float acc[4][8];
        #pragma unroll
        for (int i = 0; i < 4; i++)
            #pragma unroll
            for (int j = 0; j < 8; j++) acc[i][j] = 0.f;

        #pragma unroll 4
        for (int k = 0; k < Fq; k++) {
            float4 wa = *(const float4*)(w1t + k*128 + c0);
            float4 wb = *(const float4*)(w1t + k*128 + c0 + 4);
            #pragma unroll
            for (int i = 0; i < 4; i++) {
                float xv = xs[(r0 + i)*53 + k];
                acc[i][0] += xv * wa.x; acc[i][1] += xv * wa.y;
                acc[i][2] += xv * wa.z; acc[i][3] += xv * wa.w;
                acc[i][4] += xv * wb.x; acc[i][5] += xv * wb.y;
                acc[i][6] += xv * wb.z; acc[i][7] += xv * wb.w;
            }
        }
        #pragma unroll
        for (int i = 0; i < 4; i++)
            #pragma unroll
            for (int j = 0; j < 8; j++) {
                float v = acc[i][j] + b1s[c0 + j];
                h1s[(r0 + i)*128 + c0 + j] = v > 0.f ? v : 0.f;
            }
    }
    __syncthreads();

    // layer 2
    {
        const int cg = tid & 15, rg = tid >> 4;
        const int c0 = cg * 4, r0 = rg * 4;
        float acc[4][4];
        #pragma unroll
        for (int i = 0; i < 4; i++)
            #pragma unroll
            for (int j = 0; j < 4; j++) acc[i][j] = 0.f;

        #pragma unroll 4
        for (int k = 0; k < Hq; k++) {
            float4 w = *(const float4*)(w2t + k*64 + c0);
            #pragma unroll
            for (int i = 0; i < 4; i++) {
                float xv = h1s[(r0 + i)*128 + k];
                acc[i][0] += xv * w.x; acc[i][1] += xv * w.y;
                acc[i][2] += xv * w.z; acc[i][3] += xv * w.w;
            }
        }
        #pragma unroll
        for (int i = 0; i < 4; i++) {
            float4 o;
            float v0 = acc[i][0] + b2s[c0+0]; o.x = v0 > 0.f ? v0 : 0.f;
            float v1 = acc[i][1] + b2s[c0+1]; o.y = v1 > 0.f ? v1 : 0.f;
            float v2 = acc[i][2] + b2s[c0+2]; o.z = v2 > 0.f ? v2 : 0.f;
            float v3 = acc[i][3] + b2s[c0+3]; o.w = v3 > 0.f ? v3 : 0.f;
            *(float4*)(g_henc + (size_t)(row0 + r0 + i) * Eq + c0) = o;
        }
    }
}

// ---------------------------------------------------------------------------
// gx = h_enc @ W_ih^T + (b_ih + b_hh), written as gx[t][b][512]
// ---------------------------------------------------------------------------
#define GX_SMEM_FLOATS (64*64 + 64*128)

__global__ __launch_bounds__(256) void gx_kernel(
    const float* __restrict__ Wih,
    const float* __restrict__ bih, const float* __restrict__ bhh)
{
    extern __shared__ float sm[];
    float* hes = sm;            // [64][64]
    float* wt  = hes + 64*64;   // [64][128]

    const int tid = threadIdx.x;
    const int row0 = blockIdx.x * 64;
    const int cbase = blockIdx.y * 128;

    for (int idx = tid; idx < 64*64/4; idx += 256)
        ((float4*)hes)[idx] = ((const float4*)(g_henc + (size_t)row0 * Eq))[idx];
    for (int idx = tid; idx < 128*64; idx += 256) {
        int c = idx / 64, k = idx % 64;
        wt[k*128 + c] = Wih[(size_t)(cbase + c) * Eq + k];
    }
    __syncthreads();

    const int cg = tid & 15, rg = tid >> 4;
    const int c0 = cg * 8, r0 = rg * 4;
    float acc[4][8];
    #pragma unroll
    for (int i = 0; i < 4; i++)
        #pragma unroll
        for (int j = 0; j < 8; j++) acc[i][j] = 0.f;

    #pragma unroll 4
    for (int k = 0; k < Eq; k++) {
        float4 wa = *(const float4*)(wt + k*128 + c0);
        float4 wb = *(const float4*)(wt + k*128 + c0 + 4);
        #pragma unroll
        for (int i = 0; i < 4; i++) {
            float xv = hes[(r0 + i)*64 + k];
            acc[i][0] += xv * wa.x; acc[i][1] += xv * wa.y;
            acc[i][2] += xv * wa.z; acc[i][3] += xv * wa.w;
            acc[i][4] += xv * wb.x; acc[i][5] += xv * wb.y;
            acc[i][6] += xv * wb.z; acc[i][7] += xv * wb.w;
        }
    }

    #pragma unroll
    for (int i = 0; i < 4; i++) {
        int row = row0 + r0 + i;
        int b = row / Tq, t = row % Tq;
        size_t base = ((size_t)t * Bq + b) * G4q + cbase + c0;
        float4 oa, ob;
        oa.x = acc[i][0] + bih[cbase+c0+0] + bhh[cbase+c0+0];
        oa.y = acc[i][1] + bih[cbase+c0+1] + bhh[cbase+c0+1];
        oa.z = acc[i][2] + bih[cbase+c0+2] + bhh[cbase+c0+2];
        oa.w = acc[i][3] + bih[cbase+c0+3] + bhh[cbase+c0+3];
        ob.x = acc[i][4] + bih[cbase+c0+4] + bhh[cbase+c0+4];
        ob.y = acc[i][5] + bih[cbase+c0+5] + bhh[cbase+c0+5];
        ob.z = acc[i][6] + bih[cbase+c0+6] + bhh[cbase+c0+6];
        ob.w = acc[i][7] + bih[cbase+c0+7] + bhh[cbase+c0+7];
        *(float4*)(g_gx + base)     = oa;
        *(float4*)(g_gx + base + 4) = ob;
    }
}

// ---------------------------------------------------------------------------
// Persistent LSTM, register-resident weights.
// 64 clusters x 2 CTAs, 256 threads. Cluster cl owns batches [cl*8, cl*8+8).
// CTA rank r owns gate columns [r*64, r*64+64) for all 4 gates.
// GEMM mapping: thread = one gate-column (g = tid>>6, jl = tid&63);
//   its 128 W_hh weights live in 32 float4 REGISTERS for the whole kernel.
//   Per k4: 8 broadcast LDS.128 of h (all lanes same addr) + 32 reg-FMAs.
// Epilogue mapping: thread = (jj = tid&63, 2 batches); gate transpose goes
//   through a 9-padded smem buffer (conflict-free), then c/h update,
//   h write to self smem + peer smem (DSMEM), cluster barrier.
// ---------------------------------------------------------------------------
#define L_HS_FLOATS  (2*8*128)           // ping-pong h buffers [2][8][128]
#define L_GS_FLOATS  (256*9)             // gate transpose buffer (pad 9)
#define L_SMEM_FLOATS (L_HS_FLOATS + L_GS_FLOATS)

__global__ __launch_bounds__(256, 1) __cluster_dims__(2, 1, 1)
void lstm_persist_kernel(const float* __restrict__ Whh)
{
    extern __shared__ float sm[];
    float* hs  = sm;                  // [2][8][128]
    float* gsm = sm + L_HS_FLOATS;    // [256][9]

    const int tid = threadIdx.x;
    unsigned rank;
    asm("mov.u32 %0, %%cluster_ctarank;" : "=r"(rank));
    const int cl = blockIdx.x >> 1;          // cluster id 0..63
    const int j0 = (int)rank * 64;           // my j-half base

    // ---- load my weight row into registers (once) ----
    // column: g = tid>>6 (gate), jl = tid&63 (local j)
    const int g_own  = tid >> 6;
    const int jl_own = tid & 63;
    float4 wr[32];
    {
        const float4* wrow = (const float4*)(Whh +
            (size_t)((g_own << 7) + j0 + jl_own) * Hq);
        #pragma unroll
        for (int i = 0; i < 32; i++) wr[i] = wrow[i];
    }

    // zero h buffers
    for (int idx = tid; idx < L_HS_FLOATS; idx += 256) hs[idx] = 0.f;
    __syncthreads();
    asm volatile("barrier.cluster.arrive.aligned;" ::: "memory");
    asm volatile("barrier.cluster.wait.aligned;" ::: "memory");

    // epilogue mapping
    const int jj  = tid & 63;
    const int bg  = tid >> 6;
    const int bl0 = bg * 2;
    const int jglob = j0 + jj;

    // peer smem base for hs
    unsigned hs_loc = smem_u32(hs);
    unsigned hs_peer;
    asm("mapa.shared::cluster.u32 %0, %1, %2;"
        : "=r"(hs_peer) : "r"(hs_loc), "r"(rank ^ 1u));

    float creg[2] = {0.f, 0.f};
    int p = 0;

    const size_t gx_stride_t = (size_t)Bq * G4q;
    const float* gx_b0 = g_gx + (size_t)(cl * 8 + bl0) * G4q + jglob;

    for (int t = 0; t < Tq; t++) {
        // prefetch gx for this step (epilogue mapping; consumed after GEMM)
        const float* gxp = gx_b0 + (size_t)t * gx_stride_t;
        float gxr[2][4];
        #pragma unroll
        for (int g = 0; g < 4; g++) {
            gxr[0][g] = __ldg(gxp + g * Hq);
            gxr[1][g] = __ldg(gxp + G4q + g * Hq);
        }

        // ---- GEMM: acc[b] = sum_k h[b][k] * w_own[k], all 8 batches ----
        float acc[8];
        #pragma unroll
        for (int b = 0; b < 8; b++) acc[b] = 0.f;

        const float4* hb = (const float4*)(hs + p * 1024);  // [8][32] float4

        #pragma unroll
        for (int k4 = 0; k4 < 32; k4++) {
            float4 w = wr[k4];
            #pragma unroll
            for (int b = 0; b < 8; b++) {
                float4 h = hb[b * 32 + k4];   // broadcast: all lanes same addr
                acc[b] = fmaf(h.x, w.x, acc[b]);
                acc[b] = fmaf(h.y, w.y, acc[b]);
                acc[b] = fmaf(h.z, w.z, acc[b]);
                acc[b] = fmaf(h.w, w.w, acc[b]);
            }
        }

        // ---- gate transpose via smem (pad 9: conflict-free) ----
        {
            float* gp = gsm + tid * 9;
            #pragma unroll
            for (int b = 0; b < 8; b++) gp[b] = acc[b];
        }
        __syncthreads();

        // ---- epilogue: gates -> c,h; write h to self + peer ----
        const int pw = p ^ 1;
        #pragma unroll
        for (int b = 0; b < 2; b++) {
            int bl = bl0 + b;
            float vi = gsm[(0*64 + jj)*9 + bl] + gxr[b][0];
            float vf = gsm[(1*64 + jj)*9 + bl] + gxr[b][1];
            float vg = gsm[(2*64 + jj)*9 + bl] + gxr[b][2];
            float vo = gsm[(3*64 + jj)*9 + bl] + gxr[b][3];
            float si = sigf(vi);
            float sf = sigf(vf);
            float so = sigf(vo);
            float tg = tanhf_s(vg);
            float cn = sf * creg[b] + si * tg;
            creg[b] = cn;
            float hn = so * tanhf_s(cn);
            int off = pw * 1024 + bl * 128 + jglob;
            hs[off] = hn;
            asm volatile("st.shared::cluster.f32 [%0], %1;"
                         :: "r"(hs_peer + (unsigned)off * 4u), "f"(hn)
                         : "memory");
        }

        // step barrier: orders h writes (incl. DSMEM) before peer's reads,
        // and gsm reuse across steps
        asm volatile("barrier.cluster.arrive.aligned;" ::: "memory");
        asm volatile("barrier.cluster.wait.aligned;" ::: "memory");
        p ^= 1;
    }

    // final h is in hs[0] (512 steps, even). rank 0 publishes to global.
    if (rank == 0) {
        float* dst = g_hfin + (size_t)(cl * 8) * Hq;
        for (int idx = tid; idx < 8 * 128; idx += 256)
            dst[idx] = hs[idx];
    }
}

// ---------------------------------------------------------------------------
// Classifier: out = h_final @ Wc^T + bc, [512 x 21], K=128
// ---------------------------------------------------------------------------
__global__ void cls_kernel(const float* __restrict__ Wc,
                           const float* __restrict__ bc,
                           float* __restrict__ out)
{
    int gid = blockIdx.x * blockDim.x + threadIdx.x;
    if (gid >= Bq * 21) return;
    int b = gid / 21, c = gid % 21;
    const float* h = g_hfin + b * Hq;
    const float* w = Wc + c * Hq;
    float s = 0.f;
    #pragma unroll 8
    for (int k = 0; k < Hq; k++) s += h[k] * w[k];
    out[gid] = s + bc[c];
}

// ---------------------------------------------------------------------------
extern "C" void kernel_launch(void* const* d_in, const int* in_sizes, int n_in,
                              void* d_out, int out_size)
{
    (void)in_sizes; (void)n_in; (void)out_size;
    const float* x   = (const float*)d_in[0];
    const float* W1  = (const float*)d_in[1];
    const float* b1  = (const float*)d_in[2];
    const float* W2  = (const float*)d_in[3];
    const float* b2  = (const float*)d_in[4];
    const float* Wih = (const float*)d_in[5];
    const float* Whh = (const float*)d_in[6];
    const float* bih = (const float*)d_in[7];
    const float* bhh = (const float*)d_in[8];
    const float* Wc  = (const float*)d_in[9];
    const float* bc  = (const float*)d_in[10];
    float* out = (float*)d_out;

    cudaFuncSetAttribute(enc_kernel, cudaFuncAttributeMaxDynamicSharedMemorySize,
                         ENC_SMEM_FLOATS * (int)sizeof(float));
    cudaFuncSetAttribute(gx_kernel, cudaFuncAttributeMaxDynamicSharedMemorySize,
                         GX_SMEM_FLOATS * (int)sizeof(float));
    cudaFuncSetAttribute(lstm_persist_kernel, cudaFuncAttributeMaxDynamicSharedMemorySize,
                         L_SMEM_FLOATS * (int)sizeof(float));

    enc_kernel<<<NROWS/64, 256, ENC_SMEM_FLOATS * sizeof(float)>>>(x, W1, b1, W2, b2);

    gx_kernel<<<dim3(NROWS/64, 4), 256, GX_SMEM_FLOATS * sizeof(float)>>>(Wih, bih, bhh);

    lstm_persist_kernel<<<128, 256, L_SMEM_FLOATS * sizeof(float)>>>(Whh);

    cls_kernel<<<(Bq*21 + 255)/256, 256>>>(Wc, bc, out);
}

// round 5
// speedup vs baseline: 1.0694x; 1.0694x over previous
#include <cuda_runtime.h>
#include <stdint.h>
#include <math.h>

#define Bq 512
#define Tq 512
#define Fq 52
#define Eq 64
#define Hq 128
#define G4q 512
#define NROWS (Bq*Tq)

// Scratch (device globals; no dynamic allocation allowed)
__device__ float g_henc[NROWS * Eq];          // 64 MB  [row][64]
__device__ float g_gx[NROWS * G4q];           // 512 MB [t][b][512]
__device__ float g_hfin[Bq * Hq];             // final hidden state

// ---------------------------------------------------------------------------
// helpers
// ---------------------------------------------------------------------------
__device__ __forceinline__ unsigned smem_u32(const void* p) {
    unsigned a;
    asm("{ .reg .u64 t; cvta.to.shared.u64 t, %1; cvt.u32.u64 %0, t; }"
        : "=r"(a) : "l"(p));
    return a;
}

__device__ __forceinline__ float sigf(float x) {
    return __fdividef(1.f, 1.f + __expf(-x));
}
__device__ __forceinline__ float tanhf_s(float x) {
    float ax = fabsf(x);
    float e  = __expf(-2.f * ax);            // in (0,1], never overflows
    float r  = __fdividef(1.f - e, 1.f + e);
    return copysignf(r, x);
}

// packed f32x2 fma: d = a*b + d  (two independent fp32 FMAs, one FFMA2)
__device__ __forceinline__ void ffma2(unsigned long long& d,
                                      unsigned long long a,
                                      unsigned long long b) {
    asm("fma.rn.f32x2 %0, %1, %2, %0;" : "+l"(d) : "l"(a), "l"(b));
}
__device__ __forceinline__ float f32x2_hsum(unsigned long long v) {
    unsigned lo = (unsigned)v, hi = (unsigned)(v >> 32);
    return __uint_as_float(lo) + __uint_as_float(hi);
}

// ---------------------------------------------------------------------------
// Fused encoder: h_enc = relu(relu(x @ W1^T + b1) @ W2^T + b2)
// ---------------------------------------------------------------------------
#define ENC_SMEM_FLOATS (64*53 + 52*128 + 64*128 + 128*64 + 128 + 64)

__global__ __launch_bounds__(256) void enc_kernel(
    const float* __restrict__ x,
    const float* __restrict__ W1, const float* __restrict__ b1,
    const float* __restrict__ W2, const float* __restrict__ b2)
{
    extern __shared__ float sm[];
    float* xs  = sm;                 // [64][53]
    float* w1t = xs  + 64*53;        // [52][128]
    float* h1s = w1t + 52*128;       // [64][128]
    float* w2t = h1s + 64*128;       // [128][64]
    float* b1s = w2t + 128*64;
    float* b2s = b1s + 128;

    const int tid = threadIdx.x;
    const int row0 = blockIdx.x * 64;

    for (int idx = tid; idx < 128*52; idx += 256) {
        int c = idx / 52, k = idx % 52;
        w1t[k*128 + c] = W1[idx];
    }
    for (int idx = tid; idx < 64*128; idx += 256) {
        int e = idx / 128, k = idx % 128;
        w2t[k*64 + e] = W2[idx];
    }
    if (tid < 128) b1s[tid] = b1[tid];
    if (tid < 64)  b2s[tid] = b2[tid];
    for (int idx = tid; idx < 64*52; idx += 256) {
        int r = idx / 52, k = idx % 52;
        xs[r*53 + k] = x[(size_t)(row0 + r) * Fq + k];
    }
    __syncthreads();

    // layer 1
    {
        const int cg = tid & 15, rg = tid >> 4;
        const int c0 = cg * 8, r0 = rg * 4;
        float acc[4][8];
        #pragma unroll
        for (int i = 0; i < 4; i++)
            #pragma unroll
            for (int j = 0; j < 8; j++) acc[i][j] = 0.f;

        #pragma unroll 4
        for (int k = 0; k < Fq; k++) {
            float4 wa = *(const float4*)(w1t + k*128 + c0);
            float4 wb = *(const float4*)(w1t + k*128 + c0 + 4);
            #pragma unroll
            for (int i = 0; i < 4; i++) {
                float xv = xs[(r0 + i)*53 + k];
                acc[i][0] += xv * wa.x; acc[i][1] += xv * wa.y;
                acc[i][2] += xv * wa.z; acc[i][3] += xv * wa.w;
                acc[i][4] += xv * wb.x; acc[i][5] += xv * wb.y;
                acc[i][6] += xv * wb.z; acc[i][7] += xv * wb.w;
            }
        }
        #pragma unroll
        for (int i = 0; i < 4; i++)
            #pragma unroll
            for (int j = 0; j < 8; j++) {
                float v = acc[i][j] + b1s[c0 + j];
                h1s[(r0 + i)*128 + c0 + j] = v > 0.f ? v : 0.f;
            }
    }
    __syncthreads();

    // layer 2
    {
        const int cg = tid & 15, rg = tid >> 4;
        const int c0 = cg * 4, r0 = rg * 4;
        float acc[4][4];
        #pragma unroll
        for (int i = 0; i < 4; i++)
            #pragma unroll
            for (int j = 0; j < 4; j++) acc[i][j] = 0.f;

        #pragma unroll 4
        for (int k = 0; k < Hq; k++) {
            float4 w = *(const float4*)(w2t + k*64 + c0);
            #pragma unroll
            for (int i = 0; i < 4; i++) {
                float xv = h1s[(r0 + i)*128 + k];
                acc[i][0] += xv * w.x; acc[i][1] += xv * w.y;
                acc[i][2] += xv * w.z; acc[i][3] += xv * w.w;
            }
        }
        #pragma unroll
        for (int i = 0; i < 4; i++) {
            float4 o;
            float v0 = acc[i][0] + b2s[c0+0]; o.x = v0 > 0.f ? v0 : 0.f;
            float v1 = acc[i][1] + b2s[c0+1]; o.y = v1 > 0.f ? v1 : 0.f;
            float v2 = acc[i][2] + b2s[c0+2]; o.z = v2 > 0.f ? v2 : 0.f;
            float v3 = acc[i][3] + b2s[c0+3]; o.w = v3 > 0.f ? v3 : 0.f;
            *(float4*)(g_henc + (size_t)(row0 + r0 + i) * Eq + c0) = o;
        }
    }
}

// ---------------------------------------------------------------------------
// gx = h_enc @ W_ih^T + (b_ih + b_hh), written as gx[t][b][512]
// ---------------------------------------------------------------------------
#define GX_SMEM_FLOATS (64*64 + 64*128)

__global__ __launch_bounds__(256) void gx_kernel(
    const float* __restrict__ Wih,
    const float* __restrict__ bih, const float* __restrict__ bhh)
{
    extern __shared__ float sm[];
    float* hes = sm;            // [64][64]
    float* wt  = hes + 64*64;   // [64][128]

    const int tid = threadIdx.x;
    const int row0 = blockIdx.x * 64;
    const int cbase = blockIdx.y * 128;

    for (int idx = tid; idx < 64*64/4; idx += 256)
        ((float4*)hes)[idx] = ((const float4*)(g_henc + (size_t)row0 * Eq))[idx];
    for (int idx = tid; idx < 128*64; idx += 256) {
        int c = idx / 64, k = idx % 64;
        wt[k*128 + c] = Wih[(size_t)(cbase + c) * Eq + k];
    }
    __syncthreads();

    const int cg = tid & 15, rg = tid >> 4;
    const int c0 = cg * 8, r0 = rg * 4;
    float acc[4][8];
    #pragma unroll
    for (int i = 0; i < 4; i++)
        #pragma unroll
        for (int j = 0; j < 8; j++) acc[i][j] = 0.f;

    #pragma unroll 4
    for (int k = 0; k < Eq; k++) {
        float4 wa = *(const float4*)(wt + k*128 + c0);
        float4 wb = *(const float4*)(wt + k*128 + c0 + 4);
        #pragma unroll
        for (int i = 0; i < 4; i++) {
            float xv = hes[(r0 + i)*64 + k];
            acc[i][0] += xv * wa.x; acc[i][1] += xv * wa.y;
            acc[i][2] += xv * wa.z; acc[i][3] += xv * wa.w;
            acc[i][4] += xv * wb.x; acc[i][5] += xv * wb.y;
            acc[i][6] += xv * wb.z; acc[i][7] += xv * wb.w;
        }
    }

    #pragma unroll
    for (int i = 0; i < 4; i++) {
        int row = row0 + r0 + i;
        int b = row / Tq, t = row % Tq;
        size_t base = ((size_t)t * Bq + b) * G4q + cbase + c0;
        float4 oa, ob;
        oa.x = acc[i][0] + bih[cbase+c0+0] + bhh[cbase+c0+0];
        oa.y = acc[i][1] + bih[cbase+c0+1] + bhh[cbase+c0+1];
        oa.z = acc[i][2] + bih[cbase+c0+2] + bhh[cbase+c0+2];
        oa.w = acc[i][3] + bih[cbase+c0+3] + bhh[cbase+c0+3];
        ob.x = acc[i][4] + bih[cbase+c0+4] + bhh[cbase+c0+4];
        ob.y = acc[i][5] + bih[cbase+c0+5] + bhh[cbase+c0+5];
        ob.z = acc[i][6] + bih[cbase+c0+6] + bhh[cbase+c0+6];
        ob.w = acc[i][7] + bih[cbase+c0+7] + bhh[cbase+c0+7];
        *(float4*)(g_gx + base)     = oa;
        *(float4*)(g_gx + base + 4) = ob;
    }
}

// ---------------------------------------------------------------------------
// Persistent LSTM, register-resident weights, packed f32x2 math (FFMA2).
// 64 clusters x 2 CTAs, 256 threads. Cluster cl owns batches [cl*8, cl*8+8).
// CTA rank r owns gate columns [r*64, r*64+64) for all 4 gates.
// GEMM mapping: thread = one gate-column (g = tid>>6, jl = tid&63);
//   its 128 W_hh weights live in 64 packed f32x2 REGISTERS {w_k, w_k+1}.
//   Per k4: 8 broadcast LDS.128 of h (as double2 = two f32x2) + 16 FFMA2.
//   acc2[b] carries {sum over even k, sum over odd k}; reduced at the end.
// Epilogue mapping: thread = (jj = tid&63, 2 batches); gate transpose goes
//   through a 9-padded smem buffer, then c/h update, h write to self smem +
//   peer smem (DSMEM), cluster barrier.
// ---------------------------------------------------------------------------
#define L_HS_FLOATS  (2*8*128)           // ping-pong h buffers [2][8][128]
#define L_GS_FLOATS  (256*9)             // gate transpose buffer (pad 9)
#define L_SMEM_FLOATS (L_HS_FLOATS + L_GS_FLOATS)

__global__ __launch_bounds__(256, 1) __cluster_dims__(2, 1, 1)
void lstm_persist_kernel(const float* __restrict__ Whh)
{
    extern __shared__ float sm[];
    float* hs  = sm;                  // [2][8][128]
    float* gsm = sm + L_HS_FLOATS;    // [256][9]

    const int tid = threadIdx.x;
    unsigned rank;
    asm("mov.u32 %0, %%cluster_ctarank;" : "=r"(rank));
    const int cl = blockIdx.x >> 1;          // cluster id 0..63
    const int j0 = (int)rank * 64;           // my j-half base

    // ---- load my weight row into packed f32x2 registers (once) ----
    const int g_own  = tid >> 6;
    const int jl_own = tid & 63;
    unsigned long long wrp[64];              // {w_2i, w_2i+1}
    {
        const double2* wrow = (const double2*)(Whh +
            (size_t)((g_own << 7) + j0 + jl_own) * Hq);
        #pragma unroll
        for (int i = 0; i < 32; i++) {
            double2 wv = wrow[i];
            wrp[2*i]   = (unsigned long long)__double_as_longlong(wv.x);
            wrp[2*i+1] = (unsigned long long)__double_as_longlong(wv.y);
        }
    }

    // zero h buffers
    for (int idx = tid; idx < L_HS_FLOATS; idx += 256) hs[idx] = 0.f;
    __syncthreads();
    asm volatile("barrier.cluster.arrive.aligned;" ::: "memory");
    asm volatile("barrier.cluster.wait.aligned;" ::: "memory");

    // epilogue mapping
    const int jj  = tid & 63;
    const int bg  = tid >> 6;
    const int bl0 = bg * 2;
    const int jglob = j0 + jj;

    // peer smem base for hs
    unsigned hs_loc = smem_u32(hs);
    unsigned hs_peer;
    asm("mapa.shared::cluster.u32 %0, %1, %2;"
        : "=r"(hs_peer) : "r"(hs_loc), "r"(rank ^ 1u));

    float creg[2] = {0.f, 0.f};
    int p = 0;

    const size_t gx_stride_t = (size_t)Bq * G4q;
    const float* gx_b0 = g_gx + (size_t)(cl * 8 + bl0) * G4q + jglob;

    for (int t = 0; t < Tq; t++) {
        // prefetch gx for this step (epilogue mapping; consumed after GEMM)
        const float* gxp = gx_b0 + (size_t)t * gx_stride_t;
        float gxr[2][4];
        #pragma unroll
        for (int g = 0; g < 4; g++) {
            gxr[0][g] = __ldg(gxp + g * Hq);
            gxr[1][g] = __ldg(gxp + G4q + g * Hq);
        }

        // ---- GEMM: acc2[b] = sum_k h[b][k] * w_own[k]  (f32x2 packed) ----
        unsigned long long acc2[8];
        #pragma unroll
        for (int b = 0; b < 8; b++) acc2[b] = 0ull;   // {+0.f, +0.f}

        const double2* hbd = (const double2*)(hs + p * 1024);  // [8][32]

        #pragma unroll
        for (int k4 = 0; k4 < 32; k4++) {
            unsigned long long w01 = wrp[2*k4];
            unsigned long long w23 = wrp[2*k4+1];
            #pragma unroll
            for (int b = 0; b < 8; b++) {
                double2 hv = hbd[b * 32 + k4];   // broadcast LDS.128
                ffma2(acc2[b], (unsigned long long)__double_as_longlong(hv.x), w01);
                ffma2(acc2[b], (unsigned long long)__double_as_longlong(hv.y), w23);
            }
        }

        // ---- gate transpose via smem (pad 9: conflict-free) ----
        {
            float* gp = gsm + tid * 9;
            #pragma unroll
            for (int b = 0; b < 8; b++) gp[b] = f32x2_hsum(acc2[b]);
        }
        __syncthreads();

        // ---- epilogue: gates -> c,h; write h to self + peer ----
        const int pw = p ^ 1;
        #pragma unroll
        for (int b = 0; b < 2; b++) {
            int bl = bl0 + b;
            float vi = gsm[(0*64 + jj)*9 + bl] + gxr[b][0];
            float vf = gsm[(1*64 + jj)*9 + bl] + gxr[b][1];
            float vg = gsm[(2*64 + jj)*9 + bl] + gxr[b][2];
            float vo = gsm[(3*64 + jj)*9 + bl] + gxr[b][3];
            float si = sigf(vi);
            float sf = sigf(vf);
            float so = sigf(vo);
            float tg = tanhf_s(vg);
            float cn = sf * creg[b] + si * tg;
            creg[b] = cn;
            float hn = so * tanhf_s(cn);
            int off = pw * 1024 + bl * 128 + jglob;
            hs[off] = hn;
            asm volatile("st.shared::cluster.f32 [%0], %1;"
                         :: "r"(hs_peer + (unsigned)off * 4u), "f"(hn)
                         : "memory");
        }

        // step barrier: orders h writes (incl. DSMEM) before peer's reads,
        // and gsm reuse across steps
        asm volatile("barrier.cluster.arrive.aligned;" ::: "memory");
        asm volatile("barrier.cluster.wait.aligned;" ::: "memory");
        p ^= 1;
    }

    // final h is in hs[0] (512 steps, even). rank 0 publishes to global.
    if (rank == 0) {
        float* dst = g_hfin + (size_t)(cl * 8) * Hq;
        for (int idx = tid; idx < 8 * 128; idx += 256)
            dst[idx] = hs[idx];
    }
}

// ---------------------------------------------------------------------------
// Classifier: out = h_final @ Wc^T + bc, [512 x 21], K=128
// ---------------------------------------------------------------------------
__global__ void cls_kernel(const float* __restrict__ Wc,
                           const float* __restrict__ bc,
                           float* __restrict__ out)
{
    int gid = blockIdx.x * blockDim.x + threadIdx.x;
    if (gid >= Bq * 21) return;
    int b = gid / 21, c = gid % 21;
    const float* h = g_hfin + b * Hq;
    const float* w = Wc + c * Hq;
    float s = 0.f;
    #pragma unroll 8
    for (int k = 0; k < Hq; k++) s += h[k] * w[k];
    out[gid] = s + bc[c];
}

// ---------------------------------------------------------------------------
extern "C" void kernel_launch(void* const* d_in, const int* in_sizes, int n_in,
                              void* d_out, int out_size)
{
    (void)in_sizes; (void)n_in; (void)out_size;
    const float* x   = (const float*)d_in[0];
    const float* W1  = (const float*)d_in[1];
    const float* b1  = (const float*)d_in[2];
    const float* W2  = (const float*)d_in[3];
    const float* b2  = (const float*)d_in[4];
    const float* Wih = (const float*)d_in[5];
    const float* Whh = (const float*)d_in[6];
    const float* bih = (const float*)d_in[7];
    const float* bhh = (const float*)d_in[8];
    const float* Wc  = (const float*)d_in[9];
    const float* bc  = (const float*)d_in[10];
    float* out = (float*)d_out;

    cudaFuncSetAttribute(enc_kernel, cudaFuncAttributeMaxDynamicSharedMemorySize,
                         ENC_SMEM_FLOATS * (int)sizeof(float));
    cudaFuncSetAttribute(gx_kernel, cudaFuncAttributeMaxDynamicSharedMemorySize,
                         GX_SMEM_FLOATS * (int)sizeof(float));
    cudaFuncSetAttribute(lstm_persist_kernel, cudaFuncAttributeMaxDynamicSharedMemorySize,
                         L_SMEM_FLOATS * (int)sizeof(float));

    enc_kernel<<<NROWS/64, 256, ENC_SMEM_FLOATS * sizeof(float)>>>(x, W1, b1, W2, b2);

    gx_kernel<<<dim3(NROWS/64, 4), 256, GX_SMEM_FLOATS * sizeof(float)>>>(Wih, bih, bhh);

    lstm_persist_kernel<<<128, 256, L_SMEM_FLOATS * sizeof(float)>>>(Whh);

    cls_kernel<<<(Bq*21 + 255)/256, 256>>>(Wc, bc, out);
}